// round 2
// baseline (speedup 1.0000x reference)
#include <cuda_runtime.h>
#include <math.h>

// Problem constants
#define BB 8
#define TT 1024
#define DD 1024
#define HH 16
#define KVH 8
#define HD 64
#define M_ROWS (BB*TT)          // 8192
#define QKV_N (DD + 2*KVH*HD)   // 2048
#define FFN_N (4*DD)            // 4096

// ---------------- scratch (device globals; no allocation allowed) ----------------
__device__ float g_ln1 [M_ROWS * DD];
__device__ float g_qkv [M_ROWS * QKV_N];
__device__ float g_attn[M_ROWS * DD];
__device__ float g_h   [M_ROWS * DD];
__device__ float g_h2  [M_ROWS * DD];
__device__ float g_f1  [M_ROWS * FFN_N];

// ---------------- LayerNorm: one block per row, D=1024, 256 threads -------------
__global__ __launch_bounds__(256)
void ln_kernel(const float* __restrict__ x, const float* __restrict__ g,
               const float* __restrict__ b, float* __restrict__ y)
{
    int row = blockIdx.x;
    int t = threadIdx.x;
    const float4* xr = reinterpret_cast<const float4*>(x + (size_t)row * DD);
    float4 v = xr[t];
    float s  = v.x + v.y + v.z + v.w;
    float s2 = v.x*v.x + v.y*v.y + v.z*v.z + v.w*v.w;

    // warp reduce
    #pragma unroll
    for (int o = 16; o > 0; o >>= 1) {
        s  += __shfl_xor_sync(0xffffffffu, s,  o);
        s2 += __shfl_xor_sync(0xffffffffu, s2, o);
    }
    __shared__ float rs[8], rs2[8];
    __shared__ float s_mu, s_rstd;
    int wid = t >> 5, lane = t & 31;
    if (lane == 0) { rs[wid] = s; rs2[wid] = s2; }
    __syncthreads();
    if (t == 0) {
        float ts = 0.f, ts2 = 0.f;
        #pragma unroll
        for (int i = 0; i < 8; i++) { ts += rs[i]; ts2 += rs2[i]; }
        float mu  = ts * (1.0f / DD);
        float var = ts2 * (1.0f / DD) - mu * mu;
        s_mu = mu;
        s_rstd = rsqrtf(var + 1e-5f);
    }
    __syncthreads();
    float mu = s_mu, rstd = s_rstd;
    float4 gg = reinterpret_cast<const float4*>(g)[t];
    float4 bb = reinterpret_cast<const float4*>(b)[t];
    float4 o;
    o.x = (v.x - mu) * rstd * gg.x + bb.x;
    o.y = (v.y - mu) * rstd * gg.y + bb.y;
    o.z = (v.z - mu) * rstd * gg.z + bb.z;
    o.w = (v.w - mu) * rstd * gg.w + bb.w;
    reinterpret_cast<float4*>(y + (size_t)row * DD)[t] = o;
}

// ---------------- SGEMM: C[M,N] = A[M,K] @ W[K,N] + bias (+res) (+relu) --------
// 128x128 tile, BK=8, 256 threads, 8x8 per thread (2x2 of 4x4 sub-tiles).
template<bool RELU, bool HAS_RES>
__global__ __launch_bounds__(256)
void sgemm_kernel(const float* __restrict__ A, const float* __restrict__ W,
                  const float* __restrict__ bias, const float* __restrict__ res,
                  float* __restrict__ C, int M, int N, int K)
{
    __shared__ float As[8][128];
    __shared__ float Bs[8][128];

    int t = threadIdx.x;
    int mBase = blockIdx.y * 128;
    int nBase = blockIdx.x * 128;

    // A load mapping: row = t>>1 (0..127), kc = (t&1)*4
    int aRow = t >> 1;
    int aK   = (t & 1) * 4;
    const float* Aptr = A + (size_t)(mBase + aRow) * K + aK;
    // W load mapping: krow = t>>5 (0..7), col = (t&31)*4
    int wK   = t >> 5;
    int wCol = (t & 31) * 4;
    const float* Wptr = W + (size_t)wK * N + nBase + wCol;

    int tx = t & 15, ty = t >> 4;

    float acc[8][8];
    #pragma unroll
    for (int i = 0; i < 8; i++)
        #pragma unroll
        for (int j = 0; j < 8; j++) acc[i][j] = 0.f;

    for (int k0 = 0; k0 < K; k0 += 8) {
        float4 av = *reinterpret_cast<const float4*>(Aptr + k0);
        float4 wv = *reinterpret_cast<const float4*>(Wptr + (size_t)k0 * N);
        As[aK + 0][aRow] = av.x;
        As[aK + 1][aRow] = av.y;
        As[aK + 2][aRow] = av.z;
        As[aK + 3][aRow] = av.w;
        *reinterpret_cast<float4*>(&Bs[wK][wCol]) = wv;
        __syncthreads();

        #pragma unroll
        for (int kk = 0; kk < 8; kk++) {
            float4 a0 = *reinterpret_cast<const float4*>(&As[kk][ty * 4]);
            float4 a1 = *reinterpret_cast<const float4*>(&As[kk][ty * 4 + 64]);
            float4 b0 = *reinterpret_cast<const float4*>(&Bs[kk][tx * 4]);
            float4 b1 = *reinterpret_cast<const float4*>(&Bs[kk][tx * 4 + 64]);
            float ar[8] = {a0.x, a0.y, a0.z, a0.w, a1.x, a1.y, a1.z, a1.w};
            float br[8] = {b0.x, b0.y, b0.z, b0.w, b1.x, b1.y, b1.z, b1.w};
            #pragma unroll
            for (int i = 0; i < 8; i++)
                #pragma unroll
                for (int j = 0; j < 8; j++)
                    acc[i][j] = fmaf(ar[i], br[j], acc[i][j]);
        }
        __syncthreads();
    }

    #pragma unroll
    for (int i = 0; i < 8; i++) {
        int r = mBase + ((i < 4) ? (ty * 4 + i) : (64 + ty * 4 + i - 4));
        #pragma unroll
        for (int j = 0; j < 8; j++) {
            int c = nBase + ((j < 4) ? (tx * 4 + j) : (64 + tx * 4 + j - 4));
            float v = acc[i][j] + bias[c];
            if (HAS_RES) v += res[(size_t)r * N + c];
            if (RELU)    v = fmaxf(v, 0.f);
            C[(size_t)r * N + c] = v;
        }
    }
}

// ---------------- Attention (flash, folded 32-dim rep due to elementwise repeat)
// For query head h: K_eff[h,d] = Kflat[h*32 + d/2]; so
// score = sum_e (q[2e]+q[2e+1]) * K32[e], out[2e]=out[2e+1]=sum att*V32[e].
__global__ __launch_bounds__(64)
void attn_kernel(const float* __restrict__ qkv, float* __restrict__ out)
{
    __shared__ float Ks[64][32];
    __shared__ float Vs[64][32];
    __shared__ float Ss[64 * 65];

    int qt = blockIdx.x;             // query tile 0..15
    int bh = blockIdx.y;             // b*H + h, 0..127
    int b = bh >> 4, h = bh & 15;
    int tid = threadIdx.x;           // 0..63
    int qi = qt * 64 + tid;          // query index in [0,1024)
    size_t qrow = ((size_t)b * TT + qi) * QKV_N;

    float qf[32];
    #pragma unroll
    for (int e = 0; e < 32; e++) {
        float a = qkv[qrow + h * 64 + 2 * e];
        float c = qkv[qrow + h * 64 + 2 * e + 1];
        qf[e] = a + c;
    }

    float acc[32];
    #pragma unroll
    for (int e = 0; e < 32; e++) acc[e] = 0.f;
    float m = -INFINITY, l = 0.f;
    const float scale = 0.125f;  // 1/sqrt(64)

    for (int kt = 0; kt <= qt; kt++) {
        // load K/V tiles (64 keys x 32 dims)
        for (int idx = tid; idx < 64 * 32; idx += 64) {
            int krow = idx >> 5, col = idx & 31;
            size_t gr = ((size_t)b * TT + kt * 64 + krow) * QKV_N;
            Ks[krow][col] = qkv[gr + DD + h * 32 + col];
            Vs[krow][col] = qkv[gr + DD + KVH * HD + h * 32 + col];
        }
        __syncthreads();

        int jmax = (kt == qt) ? (tid + 1) : 64;
        float tmax = -INFINITY;
        for (int j = 0; j < jmax; j++) {
            float s = 0.f;
            #pragma unroll
            for (int e = 0; e < 32; e++) s = fmaf(qf[e], Ks[j][e], s);
            s *= scale;
            Ss[tid * 65 + j] = s;
            tmax = fmaxf(tmax, s);
        }
        float mnew = fmaxf(m, tmax);
        float cs = __expf(m - mnew);
        l *= cs;
        #pragma unroll
        for (int e = 0; e < 32; e++) acc[e] *= cs;
        for (int j = 0; j < jmax; j++) {
            float p = __expf(Ss[tid * 65 + j] - mnew);
            l += p;
            #pragma unroll
            for (int e = 0; e < 32; e++) acc[e] = fmaf(p, Vs[j][e], acc[e]);
        }
        m = mnew;
        __syncthreads();
    }

    float inv = 1.0f / l;
    size_t orow = ((size_t)b * TT + qi) * DD;
    #pragma unroll
    for (int e = 0; e < 32; e++) {
        float v = acc[e] * inv;
        out[orow + h * 64 + 2 * e]     = v;
        out[orow + h * 64 + 2 * e + 1] = v;
    }
}

// ---------------- launch -----------------------------------------------------
extern "C" void kernel_launch(void* const* d_in, const int* in_sizes, int n_in,
                              void* d_out, int out_size)
{
    const float* x     = (const float*)d_in[0];
    const float* ln1_g = (const float*)d_in[1];
    const float* ln1_b = (const float*)d_in[2];
    const float* Wqkv  = (const float*)d_in[3];
    const float* bqkv  = (const float*)d_in[4];
    const float* Wo    = (const float*)d_in[5];
    const float* bo    = (const float*)d_in[6];
    const float* ln2_g = (const float*)d_in[7];
    const float* ln2_b = (const float*)d_in[8];
    const float* W1    = (const float*)d_in[9];
    const float* b1    = (const float*)d_in[10];
    const float* W2    = (const float*)d_in[11];
    const float* b2    = (const float*)d_in[12];
    float* out = (float*)d_out;

    float *ln1, *qkv, *attn, *h, *h2, *f1;
    cudaGetSymbolAddress((void**)&ln1,  g_ln1);
    cudaGetSymbolAddress((void**)&qkv,  g_qkv);
    cudaGetSymbolAddress((void**)&attn, g_attn);
    cudaGetSymbolAddress((void**)&h,    g_h);
    cudaGetSymbolAddress((void**)&h2,   g_h2);
    cudaGetSymbolAddress((void**)&f1,   g_f1);

    // 1. ln1 = LN(x)
    ln_kernel<<<M_ROWS, 256>>>(x, ln1_g, ln1_b, ln1);
    // 2. qkv = ln1 @ Wqkv + bqkv
    sgemm_kernel<false, false><<<dim3(QKV_N / 128, M_ROWS / 128), 256>>>(
        ln1, Wqkv, bqkv, nullptr, qkv, M_ROWS, QKV_N, DD);
    // 3. attention
    attn_kernel<<<dim3(TT / 64, BB * HH), 64>>>(qkv, attn);
    // 4. h = x + attn @ Wo + bo
    sgemm_kernel<false, true><<<dim3(DD / 128, M_ROWS / 128), 256>>>(
        attn, Wo, bo, x, h, M_ROWS, DD, DD);
    // 5. h2 = LN(h)
    ln_kernel<<<M_ROWS, 256>>>(h, ln2_g, ln2_b, h2);
    // 6. f1 = relu(h2 @ W1 + b1)
    sgemm_kernel<true, false><<<dim3(FFN_N / 128, M_ROWS / 128), 256>>>(
        h2, W1, b1, nullptr, f1, M_ROWS, FFN_N, DD);
    // 7. out = x + f1 @ W2 + b2   (reference residual is x, not h!)
    sgemm_kernel<false, true><<<dim3(DD / 128, M_ROWS / 128), 256>>>(
        f1, W2, b2, x, out, M_ROWS, DD, FFN_N);
}

// round 4
// speedup vs baseline: 2.1020x; 2.1020x over previous
#include <cuda_runtime.h>
#include <math.h>

// Problem constants
#define BB 8
#define TT 1024
#define DD 1024
#define HH 16
#define KVH 8
#define HD 64
#define M_ROWS (BB*TT)          // 8192
#define QKV_N (DD + 2*KVH*HD)   // 2048
#define FFN_N (4*DD)            // 4096

// ---------------- scratch (device globals; no allocation allowed) ----------------
__device__ float g_ln1 [M_ROWS * DD];
__device__ float g_qkv [M_ROWS * QKV_N];
__device__ float g_attn[M_ROWS * DD];
__device__ float g_h   [M_ROWS * DD];
__device__ float g_h2  [M_ROWS * DD];
__device__ float g_f1  [M_ROWS * FFN_N];

// ---------------- LayerNorm: one block per row, D=1024, 256 threads -------------
__global__ __launch_bounds__(256)
void ln_kernel(const float* __restrict__ x, const float* __restrict__ g,
               const float* __restrict__ b, float* __restrict__ y)
{
    int row = blockIdx.x;
    int t = threadIdx.x;
    const float4* xr = reinterpret_cast<const float4*>(x + (size_t)row * DD);
    float4 v = xr[t];
    float s  = v.x + v.y + v.z + v.w;
    float s2 = v.x*v.x + v.y*v.y + v.z*v.z + v.w*v.w;

    #pragma unroll
    for (int o = 16; o > 0; o >>= 1) {
        s  += __shfl_xor_sync(0xffffffffu, s,  o);
        s2 += __shfl_xor_sync(0xffffffffu, s2, o);
    }
    __shared__ float rs[8], rs2[8];
    __shared__ float s_mu, s_rstd;
    int wid = t >> 5, lane = t & 31;
    if (lane == 0) { rs[wid] = s; rs2[wid] = s2; }
    __syncthreads();
    if (t == 0) {
        float ts = 0.f, ts2 = 0.f;
        #pragma unroll
        for (int i = 0; i < 8; i++) { ts += rs[i]; ts2 += rs2[i]; }
        float mu  = ts * (1.0f / DD);
        float var = ts2 * (1.0f / DD) - mu * mu;
        s_mu = mu;
        s_rstd = rsqrtf(var + 1e-5f);
    }
    __syncthreads();
    float mu = s_mu, rstd = s_rstd;
    float4 gg = reinterpret_cast<const float4*>(g)[t];
    float4 bb = reinterpret_cast<const float4*>(b)[t];
    float4 o;
    o.x = (v.x - mu) * rstd * gg.x + bb.x;
    o.y = (v.y - mu) * rstd * gg.y + bb.y;
    o.z = (v.z - mu) * rstd * gg.z + bb.z;
    o.w = (v.w - mu) * rstd * gg.w + bb.w;
    reinterpret_cast<float4*>(y + (size_t)row * DD)[t] = o;
}

// ---------------- tf32 helpers ------------------------------------------------
__device__ __forceinline__ unsigned f2tf32(float x) {
    unsigned r;
    asm("cvt.rna.tf32.f32 %0, %1;" : "=r"(r) : "f"(x));
    return r;
}
__device__ __forceinline__ uint4 cvt4(float4 v) {
    uint4 r;
    r.x = f2tf32(v.x); r.y = f2tf32(v.y); r.z = f2tf32(v.z); r.w = f2tf32(v.w);
    return r;
}
__device__ __forceinline__ void mma_tf32(float (&d)[4], const unsigned (&a)[4],
                                         const unsigned (&b)[2]) {
    asm volatile(
        "mma.sync.aligned.m16n8k8.row.col.f32.tf32.tf32.f32 "
        "{%0,%1,%2,%3}, {%4,%5,%6,%7}, {%8,%9}, {%0,%1,%2,%3};\n"
        : "+f"(d[0]), "+f"(d[1]), "+f"(d[2]), "+f"(d[3])
        : "r"(a[0]), "r"(a[1]), "r"(a[2]), "r"(a[3]), "r"(b[0]), "r"(b[1]));
}

// ---------------- TF32 tensor-core GEMM ---------------------------------------
// C[M,N] = A[M,K] @ W[K,N] + bias (+res) (+relu)
// 128x128 tile, BK=16, 256 threads = 8 warps (2x4), warp tile 64x32.
#define PAD_A 20    // BK(16)+4  -> conflict-free A fragment reads
#define PAD_B 136   // BN(128)+8 -> conflict-free B fragment reads

template<bool RELU, bool HAS_RES>
__global__ __launch_bounds__(256)
void tgemm_kernel(const float* __restrict__ A, const float* __restrict__ W,
                  const float* __restrict__ bias, const float* __restrict__ res,
                  float* __restrict__ C, int M, int N, int K)
{
    __shared__ unsigned As[128][PAD_A];
    __shared__ unsigned Bs[16][PAD_B];

    int t = threadIdx.x;
    int mBase = blockIdx.y * 128;
    int nBase = blockIdx.x * 128;
    int warp = t >> 5, lane = t & 31;
    int wm = (warp >> 2) * 64;       // 0 or 64
    int wn = (warp & 3) * 32;        // 0,32,64,96
    int lr = lane >> 2, lc = lane & 3;

    // global staging pointers (each thread: 2 float4 of A, 2 float4 of B per tile)
    int aRow = t >> 2;               // 0..63
    int aC4  = (t & 3) * 4;
    const float* Ap0 = A + (size_t)(mBase + aRow) * K + aC4;
    const float* Ap1 = Ap0 + (size_t)64 * K;
    int bRow = t >> 5;               // 0..7
    int bC4  = (t & 31) * 4;
    const float* Bp0 = W + (size_t)bRow * N + nBase + bC4;
    const float* Bp1 = Bp0 + (size_t)8 * N;

    float acc[4][4][4];
    #pragma unroll
    for (int i = 0; i < 4; i++)
        #pragma unroll
        for (int j = 0; j < 4; j++)
            #pragma unroll
            for (int k = 0; k < 4; k++) acc[i][j][k] = 0.f;

    // preload tile 0
    float4 ra0 = *reinterpret_cast<const float4*>(Ap0);
    float4 ra1 = *reinterpret_cast<const float4*>(Ap1);
    float4 rb0 = *reinterpret_cast<const float4*>(Bp0);
    float4 rb1 = *reinterpret_cast<const float4*>(Bp1);

    for (int k0 = 0; k0 < K; k0 += 16) {
        // stage (with tf32 rounding)
        *reinterpret_cast<uint4*>(&As[aRow][aC4])        = cvt4(ra0);
        *reinterpret_cast<uint4*>(&As[64 + aRow][aC4])   = cvt4(ra1);
        *reinterpret_cast<uint4*>(&Bs[bRow][bC4])        = cvt4(rb0);
        *reinterpret_cast<uint4*>(&Bs[8 + bRow][bC4])    = cvt4(rb1);
        __syncthreads();

        if (k0 + 16 < K) {
            ra0 = *reinterpret_cast<const float4*>(Ap0 + k0 + 16);
            ra1 = *reinterpret_cast<const float4*>(Ap1 + k0 + 16);
            rb0 = *reinterpret_cast<const float4*>(Bp0 + (size_t)(k0 + 16) * N);
            rb1 = *reinterpret_cast<const float4*>(Bp1 + (size_t)(k0 + 16) * N);
        }

        #pragma unroll
        for (int kc = 0; kc < 16; kc += 8) {
            unsigned af[4][4], bf[4][2];
            #pragma unroll
            for (int mt = 0; mt < 4; mt++) {
                int r = wm + mt * 16 + lr;
                af[mt][0] = As[r    ][kc + lc];
                af[mt][1] = As[r + 8][kc + lc];
                af[mt][2] = As[r    ][kc + lc + 4];
                af[mt][3] = As[r + 8][kc + lc + 4];
            }
            #pragma unroll
            for (int nt = 0; nt < 4; nt++) {
                int c = wn + nt * 8 + lr;
                bf[nt][0] = Bs[kc + lc    ][c];
                bf[nt][1] = Bs[kc + lc + 4][c];
            }
            #pragma unroll
            for (int mt = 0; mt < 4; mt++)
                #pragma unroll
                for (int nt = 0; nt < 4; nt++)
                    mma_tf32(acc[mt][nt], af[mt], bf[nt]);
        }
        __syncthreads();
    }

    // epilogue
    #pragma unroll
    for (int mt = 0; mt < 4; mt++) {
        int r0 = mBase + wm + mt * 16 + lr;
        #pragma unroll
        for (int nt = 0; nt < 4; nt++) {
            int c0 = nBase + wn + nt * 8 + lc * 2;
            float bx = bias[c0], by = bias[c0 + 1];
            float v0x = acc[mt][nt][0] + bx;
            float v0y = acc[mt][nt][1] + by;
            float v1x = acc[mt][nt][2] + bx;
            float v1y = acc[mt][nt][3] + by;
            if (HAS_RES) {
                float2 r0v = *reinterpret_cast<const float2*>(&res[(size_t)r0 * N + c0]);
                float2 r1v = *reinterpret_cast<const float2*>(&res[(size_t)(r0 + 8) * N + c0]);
                v0x += r0v.x; v0y += r0v.y; v1x += r1v.x; v1y += r1v.y;
            }
            if (RELU) {
                v0x = fmaxf(v0x, 0.f); v0y = fmaxf(v0y, 0.f);
                v1x = fmaxf(v1x, 0.f); v1y = fmaxf(v1y, 0.f);
            }
            *reinterpret_cast<float2*>(&C[(size_t)r0 * N + c0])       = make_float2(v0x, v0y);
            *reinterpret_cast<float2*>(&C[(size_t)(r0 + 8) * N + c0]) = make_float2(v1x, v1y);
        }
    }
}

// ---------------- Attention (flash, folded 32-dim rep due to elementwise repeat)
// For query head h: K_eff[h,d] = Kflat[h*32 + d/2]; so
// score = sum_e (q[2e]+q[2e+1]) * K32[e], out[2e]=out[2e+1]=sum att*V32[e].
__global__ __launch_bounds__(64)
void attn_kernel(const float* __restrict__ qkv, float* __restrict__ out)
{
    __shared__ float Ks[64][32];
    __shared__ float Vs[64][32];
    __shared__ float Ss[64 * 65];

    int qt = blockIdx.x;             // query tile 0..15
    int bh = blockIdx.y;             // b*H + h, 0..127
    int b = bh >> 4, h = bh & 15;
    int tid = threadIdx.x;           // 0..63
    int qi = qt * 64 + tid;          // query index in [0,1024)
    size_t qrow = ((size_t)b * TT + qi) * QKV_N;

    float qf[32];
    #pragma unroll
    for (int e = 0; e < 32; e++) {
        float a = qkv[qrow + h * 64 + 2 * e];
        float c = qkv[qrow + h * 64 + 2 * e + 1];
        qf[e] = a + c;
    }

    float acc[32];
    #pragma unroll
    for (int e = 0; e < 32; e++) acc[e] = 0.f;
    float m = -INFINITY, l = 0.f;
    const float scale = 0.125f;  // 1/sqrt(64)

    for (int kt = 0; kt <= qt; kt++) {
        for (int idx = tid; idx < 64 * 32; idx += 64) {
            int krow = idx >> 5, col = idx & 31;
            size_t gr = ((size_t)b * TT + kt * 64 + krow) * QKV_N;
            Ks[krow][col] = qkv[gr + DD + h * 32 + col];
            Vs[krow][col] = qkv[gr + DD + KVH * HD + h * 32 + col];
        }
        __syncthreads();

        int jmax = (kt == qt) ? (tid + 1) : 64;
        float tmax = -INFINITY;
        for (int j = 0; j < jmax; j++) {
            float s = 0.f;
            #pragma unroll
            for (int e = 0; e < 32; e++) s = fmaf(qf[e], Ks[j][e], s);
            s *= scale;
            Ss[tid * 65 + j] = s;
            tmax = fmaxf(tmax, s);
        }
        float mnew = fmaxf(m, tmax);
        float cs = __expf(m - mnew);
        l *= cs;
        #pragma unroll
        for (int e = 0; e < 32; e++) acc[e] *= cs;
        for (int j = 0; j < jmax; j++) {
            float p = __expf(Ss[tid * 65 + j] - mnew);
            l += p;
            #pragma unroll
            for (int e = 0; e < 32; e++) acc[e] = fmaf(p, Vs[j][e], acc[e]);
        }
        m = mnew;
        __syncthreads();
    }

    float inv = 1.0f / l;
    size_t orow = ((size_t)b * TT + qi) * DD;
    #pragma unroll
    for (int e = 0; e < 32; e++) {
        float v = acc[e] * inv;
        out[orow + h * 64 + 2 * e]     = v;
        out[orow + h * 64 + 2 * e + 1] = v;
    }
}

// ---------------- launch -----------------------------------------------------
extern "C" void kernel_launch(void* const* d_in, const int* in_sizes, int n_in,
                              void* d_out, int out_size)
{
    const float* x     = (const float*)d_in[0];
    const float* ln1_g = (const float*)d_in[1];
    const float* ln1_b = (const float*)d_in[2];
    const float* Wqkv  = (const float*)d_in[3];
    const float* bqkv  = (const float*)d_in[4];
    const float* Wo    = (const float*)d_in[5];
    const float* bo    = (const float*)d_in[6];
    const float* ln2_g = (const float*)d_in[7];
    const float* ln2_b = (const float*)d_in[8];
    const float* W1    = (const float*)d_in[9];
    const float* b1    = (const float*)d_in[10];
    const float* W2    = (const float*)d_in[11];
    const float* b2    = (const float*)d_in[12];
    float* out = (float*)d_out;

    float *ln1, *qkv, *attn, *h, *h2, *f1;
    cudaGetSymbolAddress((void**)&ln1,  g_ln1);
    cudaGetSymbolAddress((void**)&qkv,  g_qkv);
    cudaGetSymbolAddress((void**)&attn, g_attn);
    cudaGetSymbolAddress((void**)&h,    g_h);
    cudaGetSymbolAddress((void**)&h2,   g_h2);
    cudaGetSymbolAddress((void**)&f1,   g_f1);

    // 1. ln1 = LN(x)
    ln_kernel<<<M_ROWS, 256>>>(x, ln1_g, ln1_b, ln1);
    // 2. qkv = ln1 @ Wqkv + bqkv
    tgemm_kernel<false, false><<<dim3(QKV_N / 128, M_ROWS / 128), 256>>>(
        ln1, Wqkv, bqkv, nullptr, qkv, M_ROWS, QKV_N, DD);
    // 3. attention
    attn_kernel<<<dim3(TT / 64, BB * HH), 64>>>(qkv, attn);
    // 4. h = x + attn @ Wo + bo
    tgemm_kernel<false, true><<<dim3(DD / 128, M_ROWS / 128), 256>>>(
        attn, Wo, bo, x, h, M_ROWS, DD, DD);
    // 5. h2 = LN(h)
    ln_kernel<<<M_ROWS, 256>>>(h, ln2_g, ln2_b, h2);
    // 6. f1 = relu(h2 @ W1 + b1)
    tgemm_kernel<true, false><<<dim3(FFN_N / 128, M_ROWS / 128), 256>>>(
        h2, W1, b1, nullptr, f1, M_ROWS, FFN_N, DD);
    // 7. out = x + f1 @ W2 + b2   (reference residual is x, not h!)
    tgemm_kernel<false, true><<<dim3(DD / 128, M_ROWS / 128), 256>>>(
        f1, W2, b2, x, out, M_ROWS, DD, FFN_N);
}